// round 2
// baseline (speedup 1.0000x reference)
#include <cuda_runtime.h>
#include <cuda_bf16.h>
#include <math.h>

// Problem constants (fixed by the reference: N=50000, E=800000, F_in=128, H=4, D=64)
#define F_IN 128
#define HD   256
#define NH   4
#define ND   64
#define MAX_N 50000
#define MAX_E 800000
#define NEG_SLOPE 0.2f

// Scratch (static device globals -- no runtime allocation allowed)
__device__ float g_h[MAX_N * HD];        // projected features [N, 256]
__device__ float g_el[MAX_N * NH];
__device__ float g_er[MAX_N * NH];
__device__ int   g_deg[MAX_N + 1];
__device__ int   g_off[MAX_N + 1];
__device__ int   g_cur[MAX_N];
__device__ int   g_ssrc[MAX_E];          // src ids sorted by dst

// ---------------------------------------------------------------------------
// K1: h = feats @ W   (fp32 SGEMM, BM=64, BN=64, BK=16, 256 threads, 4x4 micro)
// ---------------------------------------------------------------------------
__global__ void gemm_kernel(const float* __restrict__ feats,
                            const float* __restrict__ W, int N) {
    __shared__ float As[16][68];   // [k][m], padded, 16B-aligned rows
    __shared__ float Bs[16][64];   // [k][n]

    const int tid = threadIdx.x;
    const int bm = blockIdx.x * 64;
    const int bn = blockIdx.y * 64;
    const int tx = tid & 15;        // 0..15
    const int ty = tid >> 4;        // 0..15

    // load indices
    const int lrow = tid >> 2;            // 0..63  (feats row within tile)
    const int lcol = (tid & 3) * 4;       // 0,4,8,12
    const int wrow = tid >> 4;            // 0..15  (W row within k-chunk)
    const int wcol = (tid & 15) * 4;      // 0..60

    float c[4][4];
#pragma unroll
    for (int i = 0; i < 4; i++)
#pragma unroll
        for (int j = 0; j < 4; j++) c[i][j] = 0.f;

    for (int kk = 0; kk < F_IN; kk += 16) {
        float4 a = make_float4(0.f, 0.f, 0.f, 0.f);
        const int gr = bm + lrow;
        if (gr < N) a = *(const float4*)(feats + (size_t)gr * F_IN + kk + lcol);
        As[lcol + 0][lrow] = a.x;
        As[lcol + 1][lrow] = a.y;
        As[lcol + 2][lrow] = a.z;
        As[lcol + 3][lrow] = a.w;

        float4 b = *(const float4*)(W + (size_t)(kk + wrow) * HD + bn + wcol);
        *(float4*)&Bs[wrow][wcol] = b;
        __syncthreads();

#pragma unroll
        for (int k = 0; k < 16; k++) {
            float4 av = *(float4*)&As[k][ty * 4];
            float4 bv = *(float4*)&Bs[k][tx * 4];
            float aa[4] = {av.x, av.y, av.z, av.w};
            float bb[4] = {bv.x, bv.y, bv.z, bv.w};
#pragma unroll
            for (int i = 0; i < 4; i++)
#pragma unroll
                for (int j = 0; j < 4; j++) c[i][j] += aa[i] * bb[j];
        }
        __syncthreads();
    }

#pragma unroll
    for (int i = 0; i < 4; i++) {
        const int gr = bm + ty * 4 + i;
        if (gr < N) {
            float4 o = make_float4(c[i][0], c[i][1], c[i][2], c[i][3]);
            *(float4*)(g_h + (size_t)gr * HD + bn + tx * 4) = o;
        }
    }
}

// ---------------------------------------------------------------------------
// K2: el[n,h] = sum_d h[n,h,d]*attn_l[h,d]; er likewise. One warp per node.
// Lane l owns h-row elements [l*8, l*8+8); head = l>>3.
// ---------------------------------------------------------------------------
__global__ void elr_kernel(const float* __restrict__ attn_l,
                           const float* __restrict__ attn_r, int N) {
    const int warp = (blockIdx.x * blockDim.x + threadIdx.x) >> 5;
    const int lane = threadIdx.x & 31;
    if (warp >= N) return;

    const float* hrow = g_h + (size_t)warp * HD + lane * 8;
    float4 v1 = *(const float4*)(hrow);
    float4 v2 = *(const float4*)(hrow + 4);
    float4 al1 = *(const float4*)(attn_l + lane * 8);
    float4 al2 = *(const float4*)(attn_l + lane * 8 + 4);
    float4 ar1 = *(const float4*)(attn_r + lane * 8);
    float4 ar2 = *(const float4*)(attn_r + lane * 8 + 4);

    float el = v1.x * al1.x + v1.y * al1.y + v1.z * al1.z + v1.w * al1.w +
               v2.x * al2.x + v2.y * al2.y + v2.z * al2.z + v2.w * al2.w;
    float er = v1.x * ar1.x + v1.y * ar1.y + v1.z * ar1.z + v1.w * ar1.w +
               v2.x * ar2.x + v2.y * ar2.y + v2.z * ar2.z + v2.w * ar2.w;

#pragma unroll
    for (int s = 1; s < 8; s <<= 1) {
        el += __shfl_xor_sync(0xffffffffu, el, s);
        er += __shfl_xor_sync(0xffffffffu, er, s);
    }
    if ((lane & 7) == 0) {
        g_el[warp * NH + (lane >> 3)] = el;
        g_er[warp * NH + (lane >> 3)] = er;
    }
}

// ---------------------------------------------------------------------------
// K3a: zero degree counters
// ---------------------------------------------------------------------------
__global__ void zero_kernel(int N) {
    int i = blockIdx.x * blockDim.x + threadIdx.x;
    if (i <= N) g_deg[i] = 0;
}

// K3b: histogram of dst
__global__ void hist_kernel(const int* __restrict__ dst, int E) {
    for (int i = blockIdx.x * blockDim.x + threadIdx.x; i < E;
         i += gridDim.x * blockDim.x)
        atomicAdd(&g_deg[dst[i]], 1);
}

// K4: single-block exclusive scan of g_deg -> g_off, g_cur
__global__ void scan_kernel(int N) {
    __shared__ int sdata[1024];
    __shared__ int s_carry;
    const int tid = threadIdx.x;
    int run = 0;
    for (int base = 0; base < N; base += 1024) {
        int v = (base + tid < N) ? g_deg[base + tid] : 0;
        sdata[tid] = v;
        __syncthreads();
#pragma unroll
        for (int off = 1; off < 1024; off <<= 1) {
            int t = (tid >= off) ? sdata[tid - off] : 0;
            __syncthreads();
            sdata[tid] += t;
            __syncthreads();
        }
        int incl = sdata[tid];
        int excl = incl - v;
        if (base + tid < N) {
            g_off[base + tid] = run + excl;
            g_cur[base + tid] = run + excl;
        }
        if (tid == 1023) s_carry = run + incl;
        __syncthreads();
        run = s_carry;
        __syncthreads();
    }
    if (tid == 0) g_off[N] = run;
}

// K5: scatter src ids into dst-sorted order
__global__ void scatter_kernel(const int* __restrict__ src,
                               const int* __restrict__ dst, int E) {
    for (int i = blockIdx.x * blockDim.x + threadIdx.x; i < E;
         i += gridDim.x * blockDim.x) {
        int d = dst[i];
        int p = atomicAdd(&g_cur[d], 1);
        g_ssrc[p] = src[i];
    }
}

// ---------------------------------------------------------------------------
// K6: per-destination softmax + weighted aggregate + head-mean + relu.
// One warp per node. Lane l owns h elements [l*8, l*8+8); head = l>>3.
// Two passes over the edge list: max, then exp/sum/accumulate.
// ---------------------------------------------------------------------------
__global__ void agg_kernel(const float* __restrict__ bias,
                           float* __restrict__ out, int N) {
    const int n = (blockIdx.x * blockDim.x + threadIdx.x) >> 5;
    const int lane = threadIdx.x & 31;
    if (n >= N) return;

    const int off = g_off[n];
    const int deg = g_deg[n];
    const int head = lane >> 3;
    const float er_n = g_er[n * NH + head];

    // Pass A: per-head max (replicated across the 8 lanes of each head)
    float m = -INFINITY;
    for (int i = 0; i < deg; i++) {
        int s = g_ssrc[off + i];
        float e = g_el[s * NH + head] + er_n;
        e = (e > 0.f) ? e : NEG_SLOPE * e;
        m = fmaxf(m, e);
    }

    // Pass B: exp-sum and weighted accumulation
    float z = 0.f;
    float acc[8];
#pragma unroll
    for (int k = 0; k < 8; k++) acc[k] = 0.f;

    for (int i = 0; i < deg; i++) {
        int s = g_ssrc[off + i];
        float e = g_el[s * NH + head] + er_n;
        e = (e > 0.f) ? e : NEG_SLOPE * e;
        float w = __expf(e - m);
        z += w;
        const float4* hp = (const float4*)(g_h + (size_t)s * HD + lane * 8);
        float4 v1 = hp[0];
        float4 v2 = hp[1];
        acc[0] += w * v1.x; acc[1] += w * v1.y;
        acc[2] += w * v1.z; acc[3] += w * v1.w;
        acc[4] += w * v2.x; acc[5] += w * v2.y;
        acc[6] += w * v2.z; acc[7] += w * v2.w;
    }

    const float inv = (z > 0.f) ? 1.0f / z : 0.0f;   // deg==0 -> acc=0, bias only
    float4 b1 = *(const float4*)(bias + lane * 8);
    float4 b2 = *(const float4*)(bias + lane * 8 + 4);
    float t[8];
    t[0] = acc[0] * inv + b1.x; t[1] = acc[1] * inv + b1.y;
    t[2] = acc[2] * inv + b1.z; t[3] = acc[3] * inv + b1.w;
    t[4] = acc[4] * inv + b2.x; t[5] = acc[5] * inv + b2.y;
    t[6] = acc[6] * inv + b2.z; t[7] = acc[7] * inv + b2.w;

    // sum over the 4 heads: lanes {l, l^8, l^16, l^24} hold the 4 head values
#pragma unroll
    for (int k = 0; k < 8; k++) {
        t[k] += __shfl_xor_sync(0xffffffffu, t[k], 8);
        t[k] += __shfl_xor_sync(0xffffffffu, t[k], 16);
    }

    if (lane < 8) {
        float4 o1, o2;
        o1.x = fmaxf(0.f, t[0] * 0.25f); o1.y = fmaxf(0.f, t[1] * 0.25f);
        o1.z = fmaxf(0.f, t[2] * 0.25f); o1.w = fmaxf(0.f, t[3] * 0.25f);
        o2.x = fmaxf(0.f, t[4] * 0.25f); o2.y = fmaxf(0.f, t[5] * 0.25f);
        o2.z = fmaxf(0.f, t[6] * 0.25f); o2.w = fmaxf(0.f, t[7] * 0.25f);
        float* op = out + (size_t)n * ND + lane * 8;
        *(float4*)(op) = o1;
        *(float4*)(op + 4) = o2;
    }
}

// ---------------------------------------------------------------------------
extern "C" void kernel_launch(void* const* d_in, const int* in_sizes, int n_in,
                              void* d_out, int out_size) {
    const float* feats  = (const float*)d_in[0];
    const int*   src    = (const int*)d_in[1];
    const int*   dst    = (const int*)d_in[2];
    const float* W      = (const float*)d_in[3];
    const float* attn_l = (const float*)d_in[4];
    const float* attn_r = (const float*)d_in[5];
    const float* bias   = (const float*)d_in[6];
    float* out = (float*)d_out;

    const int N = in_sizes[0] / F_IN;
    const int E = in_sizes[1];

    // K1: GEMM
    dim3 ggrid((N + 63) / 64, HD / 64);
    gemm_kernel<<<ggrid, 256>>>(feats, W, N);

    // K2: attention halves
    int warps_blocks = (N + 7) / 8;
    elr_kernel<<<warps_blocks, 256>>>(attn_l, attn_r, N);

    // K3: histogram
    zero_kernel<<<(N + 256) / 256, 256>>>(N);
    hist_kernel<<<512, 256>>>(dst, E);

    // K4: scan
    scan_kernel<<<1, 1024>>>(N);

    // K5: scatter into CSR
    scatter_kernel<<<512, 256>>>(src, dst, E);

    // K6: fused softmax-aggregate-mean-relu
    agg_kernel<<<warps_blocks, 256>>>(bias, out, N);
}